// round 9
// baseline (speedup 1.0000x reference)
#include <cuda_runtime.h>
#include <cuda_fp16.h>
#include <cstdint>

// ---------------------------------------------------------------------------
// MovePredictor: logits = W3 . relu(W2 . relu(W1.[e_src;e_tgt] + b1) + b2) + b3
//  - PQ = emb @ [W1_left; W1_right]^T over NODES (b1 folded into P), fp16
//  - h1[m] = relu(PQ[src,:512] + PQ[tgt,512:]) built on the fly
//  - fp16 2-pass GEMMs (weights hi+lo), mma.sync m16n8k16
//  - 128-thread CTAs (2/SM), tile 128x128, warp tile 64x64, BK=64,
//    2-stage cp.async + register fragment double-buffering.
// ---------------------------------------------------------------------------

#define N_NODES_MAX 100000
#define EMB_D   256
#define H1DIM   512
#define H2DIM   256
#define PQN     1024

#define BM 128
#define BN 128
#define BK 64
#define RS 144                   // 128B data + 16B pad
#define NT 128

#define A_O  0                   // 128*144 = 18432
#define BH_O 18432
#define BL_O 36864
#define STG  55296
#define AUXO (STG * 2)           // 110592
#define SMEM_TOTAL (AUXO + 2048)

// ---- device globals ----
__device__ __half g_PQh[(size_t)N_NODES_MAX * PQN];
__device__ __half g_Eh[(size_t)N_NODES_MAX * EMB_D];
__device__ __half g_W1sh[(size_t)PQN * EMB_D];
__device__ __half g_W1sl[(size_t)PQN * EMB_D];
__device__ __half g_W2h[(size_t)H2DIM * H1DIM];
__device__ __half g_W2l[(size_t)H2DIM * H1DIM];

// ---------------- helpers ----------------
__device__ __forceinline__ uint32_t smem_u32(const void* p) {
    uint32_t a;
    asm("{ .reg .u64 t; cvta.to.shared.u64 t, %1; cvt.u32.u64 %0, t; }"
        : "=r"(a) : "l"(p));
    return a;
}
__device__ __forceinline__ void cp16(uint32_t dst, const void* src) {
    asm volatile("cp.async.cg.shared.global [%0], [%1], 16;" :: "r"(dst), "l"(src));
}
__device__ __forceinline__ void cp_commit() {
    asm volatile("cp.async.commit_group;" ::: "memory");
}
__device__ __forceinline__ void cp_wait0() {
    asm volatile("cp.async.wait_group 0;" ::: "memory");
}
__device__ __forceinline__ void ldsm_x4(uint32_t* r, uint32_t addr) {
    asm volatile("ldmatrix.sync.aligned.m8n8.x4.shared.b16 {%0,%1,%2,%3}, [%4];"
                 : "=r"(r[0]), "=r"(r[1]), "=r"(r[2]), "=r"(r[3]) : "r"(addr));
}
__device__ __forceinline__ void mma_f16(float* c, const uint32_t* a,
                                        uint32_t b0, uint32_t b1) {
    asm volatile(
        "mma.sync.aligned.m16n8k16.row.col.f32.f16.f16.f32 "
        "{%0,%1,%2,%3}, {%4,%5,%6,%7}, {%8,%9}, {%0,%1,%2,%3};"
        : "+f"(c[0]), "+f"(c[1]), "+f"(c[2]), "+f"(c[3])
        : "r"(a[0]), "r"(a[1]), "r"(a[2]), "r"(a[3]), "r"(b0), "r"(b1));
}

// ---------------- prep ----------------
__global__ void prep_split(const float* __restrict__ emb, int n_emb,
                           const float* __restrict__ W1,
                           const float* __restrict__ W2)
{
    int total = n_emb + PQN * EMB_D + H2DIM * H1DIM;
    for (int i = blockIdx.x * blockDim.x + threadIdx.x; i < total;
         i += gridDim.x * blockDim.x) {
        if (i < n_emb) {
            g_Eh[i] = __float2half_rn(emb[i]);
        } else if (i < n_emb + PQN * EMB_D) {
            int j = i - n_emb;
            int r = j >> 8, k = j & 255;
            float x = W1[(size_t)(r & 511) * 512 + k + ((r >> 9) << 8)];
            __half h = __float2half_rn(x);
            g_W1sh[j] = h;
            g_W1sl[j] = __float2half_rn(x - __half2float(h));
        } else {
            int j = i - n_emb - PQN * EMB_D;
            float x = W2[j];
            __half h = __float2half_rn(x);
            g_W2h[j] = h;
            g_W2l[j] = __float2half_rn(x - __half2float(h));
        }
    }
}
__global__ void init_out(float* __restrict__ out, const float* __restrict__ b3, int M)
{
    int i = blockIdx.x * blockDim.x + threadIdx.x;
    if (i < M) out[i] = b3[0];
}

// MMA macro blocks ------------------------------------------------------------
#define HI_MMAS(AC)                                                            \
    _Pragma("unroll")                                                          \
    for (int mt = 0; mt < 4; mt++)                                             \
        _Pragma("unroll")                                                      \
        for (int nb = 0; nb < 4; nb++) {                                       \
            mma_f16(acc[mt][2 * nb],     AC[mt], bh[nb][0], bh[nb][2]);        \
            mma_f16(acc[mt][2 * nb + 1], AC[mt], bh[nb][1], bh[nb][3]);        \
        }
#define LO_MMAS(AC)                                                            \
    _Pragma("unroll")                                                          \
    for (int mt = 0; mt < 4; mt++)                                             \
        _Pragma("unroll")                                                      \
        for (int nb = 0; nb < 4; nb++) {                                       \
            mma_f16(acc[mt][2 * nb],     AC[mt], bl[nb][0], bl[nb][2]);        \
            mma_f16(acc[mt][2 * nb + 1], AC[mt], bl[nb][1], bl[nb][3]);        \
        }
#define LDA(dst, kt)                                                           \
    _Pragma("unroll")                                                          \
    for (int mt = 0; mt < 4; mt++)                                             \
        ldsm_x4(dst[mt], aB + mt * 16 * RS + (kt) * 32);
#define LDBH(dst, kt)                                                          \
    _Pragma("unroll")                                                          \
    for (int nb = 0; nb < 4; nb++)                                             \
        ldsm_x4(dst[nb], bB + nb * 16 * RS + (kt) * 32);
#define LDBL(kt)                                                               \
    _Pragma("unroll")                                                          \
    for (int nb = 0; nb < 4; nb++)                                             \
        ldsm_x4(bl[nb], bB + (BL_O - BH_O) + nb * 16 * RS + (kt) * 32);

// ---------------- GEMM 1: PQ = emb @ W1s^T (+b1 on P half), fp16 out ----------------
__global__ __launch_bounds__(NT, 2)
void gemm_pq(const float* __restrict__ b1, int n_nodes)
{
    extern __shared__ char sm[];
    const uint32_t sb = smem_u32(sm);
    const int t = threadIdx.x, lane = t & 31, w = t >> 5;
    const int warp_m = w >> 1, warp_n = w & 1;
    const int m0 = blockIdx.y * BM;
    const int n0 = blockIdx.x * BN;

    float acc[4][8][4];
    #pragma unroll
    for (int a = 0; a < 4; a++)
        #pragma unroll
        for (int b = 0; b < 8; b++)
            #pragma unroll
            for (int c = 0; c < 4; c++) acc[a][b][c] = 0.f;

    auto issue = [&](int stage, int ch) {
        uint32_t sg = sb + stage * STG;
        int k0 = ch * BK;
        #pragma unroll
        for (int i = 0; i < 8; i++) {            // A: 1024 cp16
            int g = t + i * NT;
            int row = g >> 3, c = g & 7;
            int gm = m0 + row; if (gm >= n_nodes) gm = n_nodes - 1;
            cp16(sg + A_O + row * RS + c * 16,
                 g_Eh + (size_t)gm * EMB_D + k0 + c * 8);
        }
        #pragma unroll
        for (int i = 0; i < 16; i++) {           // B hi+lo: 2048 cp16
            int g = t + i * NT;
            int buf = g >> 10, rem = g & 1023;
            int row = rem >> 3, c = rem & 7;
            const __half* src = (buf ? g_W1sl : g_W1sh) +
                                (size_t)(n0 + row) * EMB_D + k0 + c * 8;
            cp16(sg + (buf ? BL_O : BH_O) + row * RS + c * 16, src);
        }
        cp_commit();
    };

    const int CH = EMB_D / BK;       // 4
    issue(0, 0);
    for (int ch = 0; ch < CH; ch++) {
        cp_wait0();
        __syncthreads();
        if (ch + 1 < CH) issue((ch + 1) & 1, ch + 1);

        const uint32_t sg = sb + (ch & 1) * STG;
        const uint32_t aB = sg + A_O  + (warp_m * 64 + (lane & 15)) * RS + (lane >> 4) * 16;
        const uint32_t bB = sg + BH_O + (warp_n * 64 + (lane & 15)) * RS + (lane >> 4) * 16;
        uint32_t a0[4][4], a1[4][4], h0[4][4], h1[4][4], bl[4][4], bh_alias;
        (void)bh_alias;
        LDA(a0, 0);
        LDBH(h0, 0);
        #pragma unroll
        for (int kt = 0; kt < 4; kt++) {
            uint32_t (*ac)[4] = (kt & 1) ? a1 : a0;
            uint32_t (*an)[4] = (kt & 1) ? a0 : a1;
            uint32_t (*hc)[4] = (kt & 1) ? h1 : h0;
            uint32_t (*hn)[4] = (kt & 1) ? h0 : h1;
            if (kt < 3) { LDA(an, kt + 1); LDBH(hn, kt + 1); }
            {
                uint32_t (*bh)[4] = hc;
                HI_MMAS(ac);
            }
            LDBL(kt);
            LO_MMAS(ac);
        }
    }

    // store fp16 PQ; fold b1 into the P half (global cols < 512)
    #pragma unroll
    for (int mt = 0; mt < 4; mt++)
        #pragma unroll
        for (int h = 0; h < 2; h++) {
            int r = m0 + warp_m * 64 + mt * 16 + (lane >> 2) + 8 * h;
            if (r < n_nodes) {
                #pragma unroll
                for (int nb = 0; nb < 8; nb++) {
                    int c = n0 + warp_n * 64 + nb * 8 + (lane & 3) * 2;
                    float v0 = acc[mt][nb][2 * h];
                    float v1 = acc[mt][nb][2 * h + 1];
                    if (c < 512) { v0 += b1[c]; v1 += b1[c + 1]; }
                    *(__half2*)(g_PQh + (size_t)r * PQN + c) =
                        __floats2half2_rn(v0, v1);
                }
            }
        }
}

// ---------------- GEMM 2+3: h1 on-the-fly, GEMM vs W2 slice, relu, dot W3 ----------------
__global__ __launch_bounds__(NT, 2)
void gemm_l23(const int* __restrict__ edge_index,
              const int* __restrict__ move_idx, int n_edges,
              const float* __restrict__ b2,
              const float* __restrict__ W3, float* __restrict__ out, int M)
{
    extern __shared__ char sm[];
    const uint32_t sb = smem_u32(sm);
    const int t = threadIdx.x, lane = t & 31, w = t >> 5;
    const int warp_m = w >> 1, warp_n = w & 1;
    const int m0 = blockIdx.y * BM;
    const int n0 = blockIdx.x * BN;      // 0 or 128

    int*   offS = (int*)(sm + AUXO);
    int*   offT = (int*)(sm + AUXO + 512);
    float* b2s  = (float*)(sm + AUXO + 1024);   // 128 floats
    float* w3s  = (float*)(sm + AUXO + 1536);   // 128 floats

    {
        int m = m0 + t; if (m >= M) m = M - 1;
        int e = move_idx[m];
        offS[t] = edge_index[e] * PQN;
        offT[t] = edge_index[n_edges + e] * PQN + 512;
        b2s[t] = b2[n0 + t];
        w3s[t] = W3[n0 + t];
    }
    __syncthreads();

    float acc[4][8][4];
    #pragma unroll
    for (int a = 0; a < 4; a++)
        #pragma unroll
        for (int b = 0; b < 8; b++)
            #pragma unroll
            for (int c = 0; c < 4; c++) acc[a][b][c] = 0.f;

    const int myS = offS[t];
    const int myT = offT[t];

    auto issueB = [&](int stage, int ch) {
        uint32_t sg = sb + stage * STG;
        int k0 = ch * BK;
        #pragma unroll
        for (int i = 0; i < 16; i++) {
            int g = t + i * NT;
            int buf = g >> 10, rem = g & 1023;
            int row = rem >> 3, c = rem & 7;
            const __half* src = (buf ? g_W2l : g_W2h) +
                                (size_t)(n0 + row) * H1DIM + k0 + c * 8;
            cp16(sg + (buf ? BL_O : BH_O) + row * RS + c * 16, src);
        }
        cp_commit();
    };
    // gather half (32 cols) for chunk ch into regs
    auto ldgH = [&](int ch, int half, uint4* S, uint4* T) {
        const __half* ps = g_PQh + myS + ch * BK + half * 32;
        const __half* pt = g_PQh + myT + ch * BK + half * 32;
        #pragma unroll
        for (int q = 0; q < 4; q++) {
            S[q] = *(const uint4*)(ps + q * 8);
            T[q] = *(const uint4*)(pt + q * 8);
        }
    };
    auto stsH = [&](int stage, int half, const uint4* S, const uint4* T) {
        uint32_t o = stage * STG + A_O + t * RS + half * 64;
        const __half2 z = __floats2half2_rn(0.f, 0.f);
        #pragma unroll
        for (int q = 0; q < 4; q++) {
            uint4 v;
            const __half2* s2 = (const __half2*)&S[q];
            const __half2* t2 = (const __half2*)&T[q];
            __half2* v2 = (__half2*)&v;
            #pragma unroll
            for (int j = 0; j < 4; j++)
                v2[j] = __hmax2(__hadd2(s2[j], t2[j]), z);
            *(uint4*)(sm + o + q * 16) = v;
        }
    };

    const int CH = H1DIM / BK;       // 8
    // prologue: B chunk0 + A chunk0 into stage 0
    issueB(0, 0);
    {
        uint4 S[4], T[4];
        ldgH(0, 0, S, T); stsH(0, 0, S, T);
        ldgH(0, 1, S, T); stsH(0, 1, S, T);
    }
    for (int ch = 0; ch < CH; ch++) {
        cp_wait0();
        __syncthreads();
        const bool more = (ch + 1 < CH);
        if (more) issueB((ch + 1) & 1, ch + 1);

        const uint32_t sg = sb + (ch & 1) * STG;
        const uint32_t aB = sg + A_O  + (warp_m * 64 + (lane & 15)) * RS + (lane >> 4) * 16;
        const uint32_t bB = sg + BH_O + (warp_n * 64 + (lane & 15)) * RS + (lane >> 4) * 16;
        const int nstage = (ch + 1) & 1;

        uint32_t a0[4][4], a1[4][4], bh[4][4], bl[4][4];
        uint4 S[4], T[4];
        LDA(a0, 0);
        // ---- kt 0 ----
        if (more) ldgH(ch + 1, 0, S, T);
        LDA(a1, 1);
        LDBH(bh, 0);
        HI_MMAS(a0);
        LDBL(0);
        LO_MMAS(a0);
        // ---- kt 1 ----
        LDA(a0, 2);
        LDBH(bh, 1);
        HI_MMAS(a1);
        if (more) stsH(nstage, 0, S, T);
        LDBL(1);
        LO_MMAS(a1);
        // ---- kt 2 ----
        if (more) ldgH(ch + 1, 1, S, T);
        LDA(a1, 3);
        LDBH(bh, 2);
        HI_MMAS(a0);
        LDBL(2);
        LO_MMAS(a0);
        // ---- kt 3 ----
        LDBH(bh, 3);
        HI_MMAS(a1);
        if (more) stsH(nstage, 1, S, T);
        LDBL(3);
        LO_MMAS(a1);
    }

    // epilogue: +b2, relu, dot w3, quad-reduce, atomicAdd partials
    #pragma unroll
    for (int mt = 0; mt < 4; mt++)
        #pragma unroll
        for (int h = 0; h < 2; h++) {
            int rr = m0 + warp_m * 64 + mt * 16 + (lane >> 2) + 8 * h;
            float p = 0.f;
            #pragma unroll
            for (int nb = 0; nb < 8; nb++) {
                int c = warp_n * 64 + nb * 8 + (lane & 3) * 2;
                float v0 = acc[mt][nb][2 * h]     + b2s[c];
                float v1 = acc[mt][nb][2 * h + 1] + b2s[c + 1];
                v0 = v0 > 0.f ? v0 : 0.f;
                v1 = v1 > 0.f ? v1 : 0.f;
                p += v0 * w3s[c] + v1 * w3s[c + 1];
            }
            p += __shfl_xor_sync(0xffffffffu, p, 1);
            p += __shfl_xor_sync(0xffffffffu, p, 2);
            if ((lane & 3) == 0 && rr < M) atomicAdd(out + rr, p);
        }
}

// ---------------- launch ----------------
extern "C" void kernel_launch(void* const* d_in, const int* in_sizes, int n_in,
                              void* d_out, int out_size)
{
    const float* emb        = (const float*)d_in[0];
    const int*   edge_index = (const int*)d_in[1];
    const int*   move_idx   = (const int*)d_in[2];
    const float* W1 = (const float*)d_in[3];
    const float* b1 = (const float*)d_in[4];
    const float* W2 = (const float*)d_in[5];
    const float* b2 = (const float*)d_in[6];
    const float* W3 = (const float*)d_in[7];
    const float* b3 = (const float*)d_in[8];
    float* out = (float*)d_out;

    int n_emb   = in_sizes[0];
    int n_nodes = n_emb / EMB_D;
    int n_edges = in_sizes[1] / 2;
    int M       = in_sizes[2];
    int mtiles  = (M + BM - 1) / BM;
    int ntiles  = (n_nodes + BM - 1) / BM;

    cudaFuncSetAttribute(gemm_pq,  cudaFuncAttributeMaxDynamicSharedMemorySize, SMEM_TOTAL);
    cudaFuncSetAttribute(gemm_l23, cudaFuncAttributeMaxDynamicSharedMemorySize, SMEM_TOTAL);

    prep_split<<<512, 256>>>(emb, n_emb, W1, W2);
    init_out<<<(M + 255) / 256, 256>>>(out, b3, M);
    {
        dim3 grid(PQN / BN, ntiles);         // 8 x 782
        gemm_pq<<<grid, NT, SMEM_TOTAL>>>(b1, n_nodes);
    }
    {
        dim3 grid(H2DIM / BN, mtiles);       // 2 x 1563
        gemm_l23<<<grid, NT, SMEM_TOTAL>>>(edge_index, move_idx, n_edges,
                                           b2, W3, out, M);
    }
}

// round 10
// speedup vs baseline: 1.3050x; 1.3050x over previous
#include <cuda_runtime.h>
#include <cuda_fp16.h>
#include <cstdint>

// ---------------------------------------------------------------------------
// MovePredictor: logits = W3 . relu(W2 . relu(W1.[e_src;e_tgt] + b1) + b2) + b3
//  - PQ = emb @ [W1_left; W1_right]^T over NODES (b1 folded into P), fp16 out
//  - h1[m] = relu(PQ[src,:512] + PQ[tgt,512:]) built on the fly
//  - pq: fp16 2-pass (W1 hi+lo);  l23: fp16 1-pass (W2 hi only)
//  - R7 config: 512-thread CTAs, 16 warps, 64x32 warp tiles (CTA 128x256),
//    BK=32, 3-stage cp.async.
// ---------------------------------------------------------------------------

#define N_NODES_MAX 100000
#define EMB_D   256
#define H1DIM   512
#define H2DIM   256
#define PQN     1024

#define BM 128
#define BN 256
#define BK 32
#define RS 80
#define NT 512

// ---- pq stage layout (A + B hi + B lo) ----
#define A_O   0
#define BH_O  10240
#define BL_O  30720
#define STG1  51200
#define AUX1  (STG1 * 3)
#define SMEM1 (AUX1 + 2048)

// ---- l23 stage layout (A + B hi only) ----
#define STG2  30720
#define AUX2  (STG2 * 3)
#define SMEM2 (AUX2 + 4096)

// ---- device globals (allocation-free scratch) ----
__device__ __half g_PQh[(size_t)N_NODES_MAX * PQN];
__device__ __half g_Eh[(size_t)N_NODES_MAX * EMB_D];
__device__ __half g_W1sh[(size_t)PQN * EMB_D];
__device__ __half g_W1sl[(size_t)PQN * EMB_D];
__device__ __half g_W2h[(size_t)H2DIM * H1DIM];

// ---------------- helpers ----------------
__device__ __forceinline__ uint32_t smem_u32(const void* p) {
    uint32_t a;
    asm("{ .reg .u64 t; cvta.to.shared.u64 t, %1; cvt.u32.u64 %0, t; }"
        : "=r"(a) : "l"(p));
    return a;
}
__device__ __forceinline__ void cp16(uint32_t dst, const void* src) {
    asm volatile("cp.async.cg.shared.global [%0], [%1], 16;" :: "r"(dst), "l"(src));
}
__device__ __forceinline__ void cp_commit() {
    asm volatile("cp.async.commit_group;" ::: "memory");
}
__device__ __forceinline__ void cp_wait0() {
    asm volatile("cp.async.wait_group 0;" ::: "memory");
}
__device__ __forceinline__ void cp_wait1() {
    asm volatile("cp.async.wait_group 1;" ::: "memory");
}
__device__ __forceinline__ void ldsm_x4(uint32_t* r, uint32_t addr) {
    asm volatile("ldmatrix.sync.aligned.m8n8.x4.shared.b16 {%0,%1,%2,%3}, [%4];"
                 : "=r"(r[0]), "=r"(r[1]), "=r"(r[2]), "=r"(r[3]) : "r"(addr));
}
__device__ __forceinline__ void mma_f16(float* c, const uint32_t* a,
                                        uint32_t b0, uint32_t b1) {
    asm volatile(
        "mma.sync.aligned.m16n8k16.row.col.f32.f16.f16.f32 "
        "{%0,%1,%2,%3}, {%4,%5,%6,%7}, {%8,%9}, {%0,%1,%2,%3};"
        : "+f"(c[0]), "+f"(c[1]), "+f"(c[2]), "+f"(c[3])
        : "r"(a[0]), "r"(a[1]), "r"(a[2]), "r"(a[3]), "r"(b0), "r"(b1));
}

// 64x32 warp tile over one 32-k chunk, 2-pass (hi then lo) — for pq
__device__ __forceinline__ void mma_chunk2(uint32_t stg, int lane, int warp_m,
                                           int warp_n, float acc[4][4][4]) {
    const uint32_t aB = stg + A_O  + (warp_m * 64 + (lane & 15)) * RS + (lane >> 4) * 16;
    const uint32_t bB = stg + BH_O + (warp_n * 32 + (lane & 15)) * RS + (lane >> 4) * 16;
    #pragma unroll
    for (int kt = 0; kt < 2; kt++) {
        uint32_t aR[4][4], bH[2][4], bL[2][4];
        #pragma unroll
        for (int mt = 0; mt < 4; mt++)
            ldsm_x4(aR[mt], aB + mt * 16 * RS + kt * 32);
        #pragma unroll
        for (int nb = 0; nb < 2; nb++) {
            ldsm_x4(bH[nb], bB + nb * 16 * RS + kt * 32);
            ldsm_x4(bL[nb], bB + (BL_O - BH_O) + nb * 16 * RS + kt * 32);
        }
        #pragma unroll
        for (int mt = 0; mt < 4; mt++)
            #pragma unroll
            for (int nb = 0; nb < 2; nb++) {
                mma_f16(acc[mt][2 * nb],     aR[mt], bH[nb][0], bH[nb][2]);
                mma_f16(acc[mt][2 * nb + 1], aR[mt], bH[nb][1], bH[nb][3]);
            }
        #pragma unroll
        for (int mt = 0; mt < 4; mt++)
            #pragma unroll
            for (int nb = 0; nb < 2; nb++) {
                mma_f16(acc[mt][2 * nb],     aR[mt], bL[nb][0], bL[nb][2]);
                mma_f16(acc[mt][2 * nb + 1], aR[mt], bL[nb][1], bL[nb][3]);
            }
    }
}

// 64x32 warp tile, 1-pass (hi only) — for l23
__device__ __forceinline__ void mma_chunk1(uint32_t stg, int lane, int warp_m,
                                           int warp_n, float acc[4][4][4]) {
    const uint32_t aB = stg + A_O  + (warp_m * 64 + (lane & 15)) * RS + (lane >> 4) * 16;
    const uint32_t bB = stg + BH_O + (warp_n * 32 + (lane & 15)) * RS + (lane >> 4) * 16;
    #pragma unroll
    for (int kt = 0; kt < 2; kt++) {
        uint32_t aR[4][4], bH[2][4];
        #pragma unroll
        for (int mt = 0; mt < 4; mt++)
            ldsm_x4(aR[mt], aB + mt * 16 * RS + kt * 32);
        #pragma unroll
        for (int nb = 0; nb < 2; nb++)
            ldsm_x4(bH[nb], bB + nb * 16 * RS + kt * 32);
        #pragma unroll
        for (int mt = 0; mt < 4; mt++)
            #pragma unroll
            for (int nb = 0; nb < 2; nb++) {
                mma_f16(acc[mt][2 * nb],     aR[mt], bH[nb][0], bH[nb][2]);
                mma_f16(acc[mt][2 * nb + 1], aR[mt], bH[nb][1], bH[nb][3]);
            }
    }
}

// ---------------- prep ----------------
__global__ void prep_split(const float* __restrict__ emb, int n_emb,
                           const float* __restrict__ W1,
                           const float* __restrict__ W2)
{
    int total = n_emb + PQN * EMB_D + H2DIM * H1DIM;
    for (int i = blockIdx.x * blockDim.x + threadIdx.x; i < total;
         i += gridDim.x * blockDim.x) {
        if (i < n_emb) {
            g_Eh[i] = __float2half_rn(emb[i]);
        } else if (i < n_emb + PQN * EMB_D) {
            int j = i - n_emb;
            int r = j >> 8, k = j & 255;
            float x = W1[(size_t)(r & 511) * 512 + k + ((r >> 9) << 8)];
            __half h = __float2half_rn(x);
            g_W1sh[j] = h;
            g_W1sl[j] = __float2half_rn(x - __half2float(h));
        } else {
            int j = i - n_emb - PQN * EMB_D;
            g_W2h[j] = __float2half_rn(W2[j]);
        }
    }
}
__global__ void init_out(float* __restrict__ out, const float* __restrict__ b3, int M)
{
    int i = blockIdx.x * blockDim.x + threadIdx.x;
    if (i < M) out[i] = b3[0];
}

// ---------------- GEMM 1: PQ = emb @ W1s^T (+b1 on P half), fp16 out ----------------
__global__ __launch_bounds__(NT, 1)
void gemm_pq(const float* __restrict__ b1, int n_nodes)
{
    extern __shared__ char sm[];
    const uint32_t sb = smem_u32(sm);
    const int t = threadIdx.x, lane = t & 31, w = t >> 5;
    const int warp_m = w >> 3, warp_n = w & 7;
    const int m0 = blockIdx.y * BM;
    const int n0 = blockIdx.x * BN;

    float acc[4][4][4];
    #pragma unroll
    for (int a = 0; a < 4; a++)
        #pragma unroll
        for (int b = 0; b < 4; b++)
            #pragma unroll
            for (int c = 0; c < 4; c++) acc[a][b][c] = 0.f;

    auto issue = [&](int stage, int ch) {
        uint32_t sg = sb + stage * STG1;
        int k0 = ch * BK;
        {   // A: 512 cp16
            int row = t >> 2, c = t & 3;
            int gm = m0 + row; if (gm >= n_nodes) gm = n_nodes - 1;
            cp16(sg + A_O + row * RS + c * 16,
                 g_Eh + (size_t)gm * EMB_D + k0 + c * 8);
        }
        #pragma unroll
        for (int i = 0; i < 4; i++) {            // B hi+lo: 2048 cp16
            int g = t + i * NT;
            int buf = g >> 10, rem = g & 1023;
            int row = rem >> 2, c = rem & 3;
            const __half* src = (buf ? g_W1sl : g_W1sh) +
                                (size_t)(n0 + row) * EMB_D + k0 + c * 8;
            cp16(sg + (buf ? BL_O : BH_O) + row * RS + c * 16, src);
        }
        cp_commit();
    };

    const int CH = EMB_D / BK;       // 8
    issue(0, 0); issue(1, 1);
    for (int ch = 0; ch < CH; ch++) {
        if (ch + 2 < CH) cp_wait1(); else cp_wait0();
        __syncthreads();
        if (ch + 2 < CH) issue((ch + 2) % 3, ch + 2);
        mma_chunk2(sb + (ch % 3) * STG1, lane, warp_m, warp_n, acc);
        __syncthreads();
    }

    // store fp16 PQ; fold b1 into the P half (global cols < 512)
    #pragma unroll
    for (int mt = 0; mt < 4; mt++)
        #pragma unroll
        for (int h = 0; h < 2; h++) {
            int r = m0 + warp_m * 64 + mt * 16 + (lane >> 2) + 8 * h;
            if (r < n_nodes) {
                #pragma unroll
                for (int nb = 0; nb < 4; nb++) {
                    int c = n0 + warp_n * 32 + nb * 8 + (lane & 3) * 2;
                    float v0 = acc[mt][nb][2 * h];
                    float v1 = acc[mt][nb][2 * h + 1];
                    if (c < 512) { v0 += b1[c]; v1 += b1[c + 1]; }
                    *(__half2*)(g_PQh + (size_t)r * PQN + c) =
                        __floats2half2_rn(v0, v1);
                }
            }
        }
}

// ---------------- GEMM 2+3: h1 on-the-fly, 1-pass GEMM vs W2, relu, dot W3 ----------------
__global__ __launch_bounds__(NT, 1)
void gemm_l23(const int* __restrict__ edge_index,
              const int* __restrict__ move_idx, int n_edges,
              const float* __restrict__ b2,
              const float* __restrict__ W3, float* __restrict__ out, int M)
{
    extern __shared__ char sm[];
    const uint32_t sb = smem_u32(sm);
    const int t = threadIdx.x, lane = t & 31, w = t >> 5;
    const int warp_m = w >> 3, warp_n = w & 7;
    const int m0 = blockIdx.x * BM;

    int*   offS = (int*)(sm + AUX2);
    int*   offT = (int*)(sm + AUX2 + 512);
    float* b2s  = (float*)(sm + AUX2 + 1024);
    float* w3s  = (float*)(sm + AUX2 + 2048);

    if (t < 128) {
        int m = m0 + t; if (m >= M) m = M - 1;
        int e = move_idx[m];
        offS[t] = edge_index[e] * PQN;
        offT[t] = edge_index[n_edges + e] * PQN + 512;
    } else if (t < 384) {
        int c = t - 128;
        if (c < 256) b2s[c] = b2[c];
    }
    if (t >= 384) w3s[t - 384 + 128] = W3[t - 384 + 128];
    if (t >= 256 && t < 384) w3s[t - 256] = W3[t - 256];
    __syncthreads();

    float acc[4][4][4];
    #pragma unroll
    for (int a = 0; a < 4; a++)
        #pragma unroll
        for (int b = 0; b < 4; b++)
            #pragma unroll
            for (int c = 0; c < 4; c++) acc[a][b][c] = 0.f;

    const int r  = t >> 2;           // A row (0..127)
    const int q  = t & 3;            // 8-col group within the 32-k chunk

    auto issueB = [&](int stage, int ch) {
        uint32_t sg = sb + stage * STG2;
        int k0 = ch * BK;
        #pragma unroll
        for (int i = 0; i < 2; i++) {        // B hi: 1024 cp16
            int g = t + i * NT;
            int row = g >> 2, c = g & 3;
            cp16(sg + BH_O + row * RS + c * 16,
                 g_W2h + (size_t)row * H1DIM + k0 + c * 8);
        }
        cp_commit();
    };
    // each thread gathers 8 cols (16B) of P and Q for its row
    auto ldgA = [&](int ch, uint4& S, uint4& T) {
        int cb = ch * BK + q * 8;
        S = *(const uint4*)(g_PQh + offS[r] + cb);
        T = *(const uint4*)(g_PQh + offT[r] + cb);
    };
    auto stsA = [&](int stage, const uint4& S, const uint4& T) {
        uint32_t o = stage * STG2 + A_O + r * RS + q * 16;
        const __half2 z = __floats2half2_rn(0.f, 0.f);
        uint4 v;
        const __half2* s2 = (const __half2*)&S;
        const __half2* t2 = (const __half2*)&T;
        __half2* v2 = (__half2*)&v;
        #pragma unroll
        for (int j = 0; j < 4; j++)
            v2[j] = __hmax2(__hadd2(s2[j], t2[j]), z);
        *(uint4*)(sm + o) = v;
    };

    const int CH = H1DIM / BK;       // 16
    issueB(0, 0); issueB(1, 1);
    {
        uint4 S, T;
        ldgA(0, S, T);
        stsA(0, S, T);
    }
    for (int ch = 0; ch < CH; ch++) {
        if (ch + 2 < CH) cp_wait1(); else cp_wait0();
        __syncthreads();
        if (ch + 2 < CH) issueB((ch + 2) % 3, ch + 2);
        uint4 S, T;
        const bool more = (ch + 1 < CH);
        if (more) ldgA(ch + 1, S, T);
        mma_chunk1(sb + (ch % 3) * STG2, lane, warp_m, warp_n, acc);
        if (more) stsA((ch + 1) % 3, S, T);
    }

    // epilogue: +b2, relu, dot w3, quad-reduce, atomicAdd
    #pragma unroll
    for (int mt = 0; mt < 4; mt++)
        #pragma unroll
        for (int h = 0; h < 2; h++) {
            int rr = m0 + warp_m * 64 + mt * 16 + (lane >> 2) + 8 * h;
            float p = 0.f;
            #pragma unroll
            for (int nb = 0; nb < 4; nb++) {
                int c = warp_n * 32 + nb * 8 + (lane & 3) * 2;
                float v0 = acc[mt][nb][2 * h]     + b2s[c];
                float v1 = acc[mt][nb][2 * h + 1] + b2s[c + 1];
                v0 = v0 > 0.f ? v0 : 0.f;
                v1 = v1 > 0.f ? v1 : 0.f;
                p += v0 * w3s[c] + v1 * w3s[c + 1];
            }
            p += __shfl_xor_sync(0xffffffffu, p, 1);
            p += __shfl_xor_sync(0xffffffffu, p, 2);
            if ((lane & 3) == 0 && rr < M) atomicAdd(out + rr, p);
        }
}

// ---------------- launch ----------------
extern "C" void kernel_launch(void* const* d_in, const int* in_sizes, int n_in,
                              void* d_out, int out_size)
{
    const float* emb        = (const float*)d_in[0];
    const int*   edge_index = (const int*)d_in[1];
    const int*   move_idx   = (const int*)d_in[2];
    const float* W1 = (const float*)d_in[3];
    const float* b1 = (const float*)d_in[4];
    const float* W2 = (const float*)d_in[5];
    const float* b2 = (const float*)d_in[6];
    const float* W3 = (const float*)d_in[7];
    const float* b3 = (const float*)d_in[8];
    float* out = (float*)d_out;

    int n_emb   = in_sizes[0];
    int n_nodes = n_emb / EMB_D;
    int n_edges = in_sizes[1] / 2;
    int M       = in_sizes[2];
    int mtiles  = (M + BM - 1) / BM;
    int ntiles  = (n_nodes + BM - 1) / BM;

    cudaFuncSetAttribute(gemm_pq,  cudaFuncAttributeMaxDynamicSharedMemorySize, SMEM1);
    cudaFuncSetAttribute(gemm_l23, cudaFuncAttributeMaxDynamicSharedMemorySize, SMEM2);

    prep_split<<<512, 256>>>(emb, n_emb, W1, W2);
    init_out<<<(M + 255) / 256, 256>>>(out, b3, M);
    {
        dim3 grid(PQN / BN, ntiles);     // 4 x 782
        gemm_pq<<<grid, NT, SMEM1>>>(b1, n_nodes);
    }
    gemm_l23<<<mtiles, NT, SMEM2>>>(edge_index, move_idx, n_edges,
                                    b2, W3, out, M);
}

// round 11
// speedup vs baseline: 1.5991x; 1.2254x over previous
#include <cuda_runtime.h>
#include <cuda_fp16.h>
#include <cstdint>

// ---------------------------------------------------------------------------
// MovePredictor: logits = W3 . relu(W2 . relu(W1.[e_src;e_tgt] + b1) + b2) + b3
//  - PQ = emb @ [W1_left; W1_right]^T over NODES (b1 folded into P), fp16 out
//  - h1[m] = relu(PQ[src,:512] + PQ[tgt,512:]) built on the fly
//  - 1-pass fp16 GEMMs (weights hi only) in both stages
//  - 512-thread CTAs, 16 warps, 64x32 warp tiles (CTA 128x256), BK=32,
//    3-stage cp.async; l23 epilogue via smem reduction (no atomics).
// ---------------------------------------------------------------------------

#define N_NODES_MAX 100000
#define EMB_D   256
#define H1DIM   512
#define H2DIM   256
#define PQN     1024

#define BM 128
#define BN 256
#define BK 32
#define RS 80
#define NT 512

// stage layout: A (128x80) + B hi (256x80)
#define A_O   0
#define BH_O  10240
#define STG   30720
#define AUXO  (STG * 3)          // 92160
#define SMEM_TOTAL (AUXO + 8192)

// ---- device globals (allocation-free scratch) ----
__device__ __half g_PQh[(size_t)N_NODES_MAX * PQN];
__device__ __half g_Eh[(size_t)N_NODES_MAX * EMB_D];
__device__ __half g_W1sh[(size_t)PQN * EMB_D];
__device__ __half g_W2h[(size_t)H2DIM * H1DIM];

// ---------------- helpers ----------------
__device__ __forceinline__ uint32_t smem_u32(const void* p) {
    uint32_t a;
    asm("{ .reg .u64 t; cvta.to.shared.u64 t, %1; cvt.u32.u64 %0, t; }"
        : "=r"(a) : "l"(p));
    return a;
}
__device__ __forceinline__ void cp16(uint32_t dst, const void* src) {
    asm volatile("cp.async.cg.shared.global [%0], [%1], 16;" :: "r"(dst), "l"(src));
}
__device__ __forceinline__ void cp_commit() {
    asm volatile("cp.async.commit_group;" ::: "memory");
}
__device__ __forceinline__ void cp_wait0() {
    asm volatile("cp.async.wait_group 0;" ::: "memory");
}
__device__ __forceinline__ void cp_wait1() {
    asm volatile("cp.async.wait_group 1;" ::: "memory");
}
__device__ __forceinline__ void ldsm_x4(uint32_t* r, uint32_t addr) {
    asm volatile("ldmatrix.sync.aligned.m8n8.x4.shared.b16 {%0,%1,%2,%3}, [%4];"
                 : "=r"(r[0]), "=r"(r[1]), "=r"(r[2]), "=r"(r[3]) : "r"(addr));
}
__device__ __forceinline__ void mma_f16(float* c, const uint32_t* a,
                                        uint32_t b0, uint32_t b1) {
    asm volatile(
        "mma.sync.aligned.m16n8k16.row.col.f32.f16.f16.f32 "
        "{%0,%1,%2,%3}, {%4,%5,%6,%7}, {%8,%9}, {%0,%1,%2,%3};"
        : "+f"(c[0]), "+f"(c[1]), "+f"(c[2]), "+f"(c[3])
        : "r"(a[0]), "r"(a[1]), "r"(a[2]), "r"(a[3]), "r"(b0), "r"(b1));
}

// 64x32 warp tile over one 32-k chunk, 1-pass (hi only)
__device__ __forceinline__ void mma_chunk1(uint32_t stg, int lane, int warp_m,
                                           int warp_n, float acc[4][4][4]) {
    const uint32_t aB = stg + A_O  + (warp_m * 64 + (lane & 15)) * RS + (lane >> 4) * 16;
    const uint32_t bB = stg + BH_O + (warp_n * 32 + (lane & 15)) * RS + (lane >> 4) * 16;
    #pragma unroll
    for (int kt = 0; kt < 2; kt++) {
        uint32_t aR[4][4], bH[2][4];
        #pragma unroll
        for (int mt = 0; mt < 4; mt++)
            ldsm_x4(aR[mt], aB + mt * 16 * RS + kt * 32);
        #pragma unroll
        for (int nb = 0; nb < 2; nb++)
            ldsm_x4(bH[nb], bB + nb * 16 * RS + kt * 32);
        #pragma unroll
        for (int mt = 0; mt < 4; mt++)
            #pragma unroll
            for (int nb = 0; nb < 2; nb++) {
                mma_f16(acc[mt][2 * nb],     aR[mt], bH[nb][0], bH[nb][2]);
                mma_f16(acc[mt][2 * nb + 1], aR[mt], bH[nb][1], bH[nb][3]);
            }
    }
}

// ---------------- prep ----------------
__global__ void prep_split(const float* __restrict__ emb, int n_emb,
                           const float* __restrict__ W1,
                           const float* __restrict__ W2)
{
    int total = n_emb + PQN * EMB_D + H2DIM * H1DIM;
    for (int i = blockIdx.x * blockDim.x + threadIdx.x; i < total;
         i += gridDim.x * blockDim.x) {
        if (i < n_emb) {
            g_Eh[i] = __float2half_rn(emb[i]);
        } else if (i < n_emb + PQN * EMB_D) {
            int j = i - n_emb;
            int r = j >> 8, k = j & 255;
            g_W1sh[j] = __float2half_rn(
                W1[(size_t)(r & 511) * 512 + k + ((r >> 9) << 8)]);
        } else {
            int j = i - n_emb - PQN * EMB_D;
            g_W2h[j] = __float2half_rn(W2[j]);
        }
    }
}

// ---------------- GEMM 1: PQ = emb @ W1s^T (+b1 on P half), fp16 out ----------------
__global__ __launch_bounds__(NT, 1)
void gemm_pq(const float* __restrict__ b1, int n_nodes)
{
    extern __shared__ char sm[];
    const uint32_t sb = smem_u32(sm);
    const int t = threadIdx.x, lane = t & 31, w = t >> 5;
    const int warp_m = w >> 3, warp_n = w & 7;
    const int m0 = blockIdx.y * BM;
    const int n0 = blockIdx.x * BN;

    float acc[4][4][4];
    #pragma unroll
    for (int a = 0; a < 4; a++)
        #pragma unroll
        for (int b = 0; b < 4; b++)
            #pragma unroll
            for (int c = 0; c < 4; c++) acc[a][b][c] = 0.f;

    auto issue = [&](int stage, int ch) {
        uint32_t sg = sb + stage * STG;
        int k0 = ch * BK;
        {   // A: 512 cp16
            int row = t >> 2, c = t & 3;
            int gm = m0 + row; if (gm >= n_nodes) gm = n_nodes - 1;
            cp16(sg + A_O + row * RS + c * 16,
                 g_Eh + (size_t)gm * EMB_D + k0 + c * 8);
        }
        #pragma unroll
        for (int i = 0; i < 2; i++) {            // B hi: 1024 cp16
            int g = t + i * NT;
            int row = g >> 2, c = g & 3;
            cp16(sg + BH_O + row * RS + c * 16,
                 g_W1sh + (size_t)(n0 + row) * EMB_D + k0 + c * 8);
        }
        cp_commit();
    };

    const int CH = EMB_D / BK;       // 8
    issue(0, 0); issue(1, 1);
    for (int ch = 0; ch < CH; ch++) {
        if (ch + 2 < CH) cp_wait1(); else cp_wait0();
        __syncthreads();
        if (ch + 2 < CH) issue((ch + 2) % 3, ch + 2);
        mma_chunk1(sb + (ch % 3) * STG, lane, warp_m, warp_n, acc);
        __syncthreads();
    }

    // store fp16 PQ; fold b1 into the P half (global cols < 512)
    #pragma unroll
    for (int mt = 0; mt < 4; mt++)
        #pragma unroll
        for (int h = 0; h < 2; h++) {
            int r = m0 + warp_m * 64 + mt * 16 + (lane >> 2) + 8 * h;
            if (r < n_nodes) {
                #pragma unroll
                for (int nb = 0; nb < 4; nb++) {
                    int c = n0 + warp_n * 32 + nb * 8 + (lane & 3) * 2;
                    float v0 = acc[mt][nb][2 * h];
                    float v1 = acc[mt][nb][2 * h + 1];
                    if (c < 512) { v0 += b1[c]; v1 += b1[c + 1]; }
                    *(__half2*)(g_PQh + (size_t)r * PQN + c) =
                        __floats2half2_rn(v0, v1);
                }
            }
        }
}

// ---------------- GEMM 2+3: h1 on-the-fly, 1-pass GEMM vs W2, relu, dot W3 ----------------
__global__ __launch_bounds__(NT, 1)
void gemm_l23(const int* __restrict__ edge_index,
              const int* __restrict__ move_idx, int n_edges,
              const float* __restrict__ b2,
              const float* __restrict__ W3, const float* __restrict__ b3,
              float* __restrict__ out, int M)
{
    extern __shared__ char sm[];
    const uint32_t sb = smem_u32(sm);
    const int t = threadIdx.x, lane = t & 31, w = t >> 5;
    const int warp_m = w >> 3, warp_n = w & 7;
    const int m0 = blockIdx.x * BM;

    int*   offS = (int*)(sm + AUXO);
    int*   offT = (int*)(sm + AUXO + 512);
    float* b2s  = (float*)(sm + AUXO + 1024);
    float* w3s  = (float*)(sm + AUXO + 2048);
    float* red  = (float*)(sm + AUXO + 4096);   // [128][8]

    if (t < 128) {
        int m = m0 + t; if (m >= M) m = M - 1;
        int e = move_idx[m];
        offS[t] = edge_index[e] * PQN;
        offT[t] = edge_index[n_edges + e] * PQN + 512;
    } else if (t < 384) {
        b2s[t - 128] = b2[t - 128];
    } else {
        // covered below
    }
    if (t >= 256) w3s[t - 256] = W3[t - 256];
    __syncthreads();

    float acc[4][4][4];
    #pragma unroll
    for (int a = 0; a < 4; a++)
        #pragma unroll
        for (int b = 0; b < 4; b++)
            #pragma unroll
            for (int c = 0; c < 4; c++) acc[a][b][c] = 0.f;

    const int r = t >> 2;            // A row (0..127)
    const int q = t & 3;             // 8-col group within the 32-k chunk

    auto issueB = [&](int stage, int ch) {
        uint32_t sg = sb + stage * STG;
        int k0 = ch * BK;
        #pragma unroll
        for (int i = 0; i < 2; i++) {        // B hi: 1024 cp16
            int g = t + i * NT;
            int row = g >> 2, c = g & 3;
            cp16(sg + BH_O + row * RS + c * 16,
                 g_W2h + (size_t)row * H1DIM + k0 + c * 8);
        }
        cp_commit();
    };
    auto ldgA = [&](int ch, uint4& S, uint4& T) {
        int cb = ch * BK + q * 8;
        S = *(const uint4*)(g_PQh + offS[r] + cb);
        T = *(const uint4*)(g_PQh + offT[r] + cb);
    };
    auto stsA = [&](int stage, const uint4& S, const uint4& T) {
        uint32_t o = stage * STG + A_O + r * RS + q * 16;
        const __half2 z = __floats2half2_rn(0.f, 0.f);
        uint4 v;
        const __half2* s2 = (const __half2*)&S;
        const __half2* t2 = (const __half2*)&T;
        __half2* v2 = (__half2*)&v;
        #pragma unroll
        for (int j = 0; j < 4; j++)
            v2[j] = __hmax2(__hadd2(s2[j], t2[j]), z);
        *(uint4*)(sm + o) = v;
    };

    const int CH = H1DIM / BK;       // 16
    issueB(0, 0); issueB(1, 1);
    {
        uint4 S, T;
        ldgA(0, S, T);
        stsA(0, S, T);
    }
    for (int ch = 0; ch < CH; ch++) {
        if (ch + 2 < CH) cp_wait1(); else cp_wait0();
        __syncthreads();
        if (ch + 2 < CH) issueB((ch + 2) % 3, ch + 2);
        uint4 S, T;
        const bool more = (ch + 1 < CH);
        if (more) ldgA(ch + 1, S, T);
        mma_chunk1(sb + (ch % 3) * STG, lane, warp_m, warp_n, acc);
        if (more) stsA((ch + 1) % 3, S, T);
    }

    // epilogue: +b2, relu, dot w3, quad-reduce, smem partials per warp_n
    #pragma unroll
    for (int mt = 0; mt < 4; mt++)
        #pragma unroll
        for (int h = 0; h < 2; h++) {
            int ri = warp_m * 64 + mt * 16 + (lane >> 2) + 8 * h;   // 0..127
            float p = 0.f;
            #pragma unroll
            for (int nb = 0; nb < 4; nb++) {
                int c = warp_n * 32 + nb * 8 + (lane & 3) * 2;
                float v0 = acc[mt][nb][2 * h]     + b2s[c];
                float v1 = acc[mt][nb][2 * h + 1] + b2s[c + 1];
                v0 = v0 > 0.f ? v0 : 0.f;
                v1 = v1 > 0.f ? v1 : 0.f;
                p += v0 * w3s[c] + v1 * w3s[c + 1];
            }
            p += __shfl_xor_sync(0xffffffffu, p, 1);
            p += __shfl_xor_sync(0xffffffffu, p, 2);
            if ((lane & 3) == 0) red[ri * 8 + warp_n] = p;
        }
    __syncthreads();
    if (t < 128) {
        int m = m0 + t;
        if (m < M) {
            float s = b3[0];
            #pragma unroll
            for (int j = 0; j < 8; j++) s += red[t * 8 + j];
            out[m] = s;
        }
    }
}

// ---------------- launch ----------------
extern "C" void kernel_launch(void* const* d_in, const int* in_sizes, int n_in,
                              void* d_out, int out_size)
{
    const float* emb        = (const float*)d_in[0];
    const int*   edge_index = (const int*)d_in[1];
    const int*   move_idx   = (const int*)d_in[2];
    const float* W1 = (const float*)d_in[3];
    const float* b1 = (const float*)d_in[4];
    const float* W2 = (const float*)d_in[5];
    const float* b2 = (const float*)d_in[6];
    const float* W3 = (const float*)d_in[7];
    const float* b3 = (const float*)d_in[8];
    float* out = (float*)d_out;

    int n_emb   = in_sizes[0];
    int n_nodes = n_emb / EMB_D;
    int n_edges = in_sizes[1] / 2;
    int M       = in_sizes[2];
    int mtiles  = (M + BM - 1) / BM;
    int ntiles  = (n_nodes + BM - 1) / BM;

    cudaFuncSetAttribute(gemm_pq,  cudaFuncAttributeMaxDynamicSharedMemorySize, SMEM_TOTAL);
    cudaFuncSetAttribute(gemm_l23, cudaFuncAttributeMaxDynamicSharedMemorySize, SMEM_TOTAL);

    prep_split<<<512, 256>>>(emb, n_emb, W1, W2);
    {
        dim3 grid(PQN / BN, ntiles);     // 4 x 782
        gemm_pq<<<grid, NT, SMEM_TOTAL>>>(b1, n_nodes);
    }
    gemm_l23<<<mtiles, NT, SMEM_TOTAL>>>(edge_index, move_idx, n_edges,
                                         b2, W3, b3, out, M);
}

// round 12
// speedup vs baseline: 1.9058x; 1.1917x over previous
#include <cuda_runtime.h>
#include <cuda_fp16.h>
#include <cstdint>

// ---------------------------------------------------------------------------
// MovePredictor: logits = W3 . relu(W2 . relu(W1.[e_src;e_tgt] + b1) + b2) + b3
//  - PQ = emb @ [W1_left; W1_right]^T over NODES (b1 folded into P), fp16 out
//  - pq consumes emb fp32 directly (LDG->CVT->STS pipelined A path)
//  - h1[m] = relu(PQ[src,:512] + PQ[tgt,512:]) built on the fly
//  - 1-pass fp16 GEMMs, 512-thread CTAs, 64x32 warp tiles (CTA 128x256),
//    BK=32, 3-stage cp.async for B; smem-reduction epilogue in l23.
// ---------------------------------------------------------------------------

#define N_NODES_MAX 100000
#define EMB_D   256
#define H1DIM   512
#define H2DIM   256
#define PQN     1024

#define BM 128
#define BN 256
#define BK 32
#define RS 80
#define NT 512

// stage layout: A (128x80) + B hi (256x80)
#define A_O   0
#define BH_O  10240
#define STG   30720
#define AUXO  (STG * 3)          // 92160
#define SMEM_TOTAL (AUXO + 8192)

// ---- device globals (allocation-free scratch) ----
__device__ __half g_PQh[(size_t)N_NODES_MAX * PQN];
__device__ __half g_W1sh[(size_t)PQN * EMB_D];
__device__ __half g_W2h[(size_t)H2DIM * H1DIM];

// ---------------- helpers ----------------
__device__ __forceinline__ uint32_t smem_u32(const void* p) {
    uint32_t a;
    asm("{ .reg .u64 t; cvta.to.shared.u64 t, %1; cvt.u32.u64 %0, t; }"
        : "=r"(a) : "l"(p));
    return a;
}
__device__ __forceinline__ void cp16(uint32_t dst, const void* src) {
    asm volatile("cp.async.cg.shared.global [%0], [%1], 16;" :: "r"(dst), "l"(src));
}
__device__ __forceinline__ void cp_commit() {
    asm volatile("cp.async.commit_group;" ::: "memory");
}
__device__ __forceinline__ void cp_wait0() {
    asm volatile("cp.async.wait_group 0;" ::: "memory");
}
__device__ __forceinline__ void cp_wait1() {
    asm volatile("cp.async.wait_group 1;" ::: "memory");
}
__device__ __forceinline__ void ldsm_x4(uint32_t* r, uint32_t addr) {
    asm volatile("ldmatrix.sync.aligned.m8n8.x4.shared.b16 {%0,%1,%2,%3}, [%4];"
                 : "=r"(r[0]), "=r"(r[1]), "=r"(r[2]), "=r"(r[3]) : "r"(addr));
}
__device__ __forceinline__ void mma_f16(float* c, const uint32_t* a,
                                        uint32_t b0, uint32_t b1) {
    asm volatile(
        "mma.sync.aligned.m16n8k16.row.col.f32.f16.f16.f32 "
        "{%0,%1,%2,%3}, {%4,%5,%6,%7}, {%8,%9}, {%0,%1,%2,%3};"
        : "+f"(c[0]), "+f"(c[1]), "+f"(c[2]), "+f"(c[3])
        : "r"(a[0]), "r"(a[1]), "r"(a[2]), "r"(a[3]), "r"(b0), "r"(b1));
}

// 64x32 warp tile over one 32-k chunk, 1-pass (hi only)
__device__ __forceinline__ void mma_chunk1(uint32_t stg, int lane, int warp_m,
                                           int warp_n, float acc[4][4][4]) {
    const uint32_t aB = stg + A_O  + (warp_m * 64 + (lane & 15)) * RS + (lane >> 4) * 16;
    const uint32_t bB = stg + BH_O + (warp_n * 32 + (lane & 15)) * RS + (lane >> 4) * 16;
    #pragma unroll
    for (int kt = 0; kt < 2; kt++) {
        uint32_t aR[4][4], bH[2][4];
        #pragma unroll
        for (int mt = 0; mt < 4; mt++)
            ldsm_x4(aR[mt], aB + mt * 16 * RS + kt * 32);
        #pragma unroll
        for (int nb = 0; nb < 2; nb++)
            ldsm_x4(bH[nb], bB + nb * 16 * RS + kt * 32);
        #pragma unroll
        for (int mt = 0; mt < 4; mt++)
            #pragma unroll
            for (int nb = 0; nb < 2; nb++) {
                mma_f16(acc[mt][2 * nb],     aR[mt], bH[nb][0], bH[nb][2]);
                mma_f16(acc[mt][2 * nb + 1], aR[mt], bH[nb][1], bH[nb][3]);
            }
    }
}

// ---------------- prep: weights only ----------------
__global__ void prep_w(const float* __restrict__ W1, const float* __restrict__ W2)
{
    int total = PQN * EMB_D + H2DIM * H1DIM;     // 393216
    for (int i = blockIdx.x * blockDim.x + threadIdx.x; i < total;
         i += gridDim.x * blockDim.x) {
        if (i < PQN * EMB_D) {
            int r = i >> 8, k = i & 255;
            g_W1sh[i] = __float2half_rn(
                W1[(size_t)(r & 511) * 512 + k + ((r >> 9) << 8)]);
        } else {
            int j = i - PQN * EMB_D;
            g_W2h[j] = __float2half_rn(W2[j]);
        }
    }
}

// ---------------- GEMM 1: PQ = emb @ W1s^T (+b1 on P half), fp16 out ----------------
__global__ __launch_bounds__(NT, 1)
void gemm_pq(const float* __restrict__ emb, const float* __restrict__ b1,
             int n_nodes)
{
    extern __shared__ char sm[];
    const uint32_t sb = smem_u32(sm);
    const int t = threadIdx.x, lane = t & 31, w = t >> 5;
    const int warp_m = w >> 3, warp_n = w & 7;
    const int m0 = blockIdx.y * BM;
    const int n0 = blockIdx.x * BN;

    float acc[4][4][4];
    #pragma unroll
    for (int a = 0; a < 4; a++)
        #pragma unroll
        for (int b = 0; b < 4; b++)
            #pragma unroll
            for (int c = 0; c < 4; c++) acc[a][b][c] = 0.f;

    // A path: per-thread LDG of 8 fp32 -> cvt -> 16B STS
    const int ar = t >> 2;           // A row (0..127)
    const int aq = t & 3;            // 8-col group
    int gm = m0 + ar; if (gm >= n_nodes) gm = n_nodes - 1;
    const float* embRow = emb + (size_t)gm * EMB_D + aq * 8;

    auto issueB = [&](int stage, int ch) {
        uint32_t sg = sb + stage * STG;
        int k0 = ch * BK;
        #pragma unroll
        for (int i = 0; i < 2; i++) {        // B hi: 1024 cp16
            int g = t + i * NT;
            int row = g >> 2, c = g & 3;
            cp16(sg + BH_O + row * RS + c * 16,
                 g_W1sh + (size_t)(n0 + row) * EMB_D + k0 + c * 8);
        }
        cp_commit();
    };
    auto ldgA = [&](int ch, float4& X0, float4& X1) {
        const float* p = embRow + ch * BK;
        X0 = *(const float4*)p;
        X1 = *(const float4*)(p + 4);
    };
    auto stsA = [&](int stage, const float4& X0, const float4& X1) {
        uint32_t o = stage * STG + A_O + ar * RS + aq * 16;
        uint4 v;
        __half2* v2 = (__half2*)&v;
        v2[0] = __floats2half2_rn(X0.x, X0.y);
        v2[1] = __floats2half2_rn(X0.z, X0.w);
        v2[2] = __floats2half2_rn(X1.x, X1.y);
        v2[3] = __floats2half2_rn(X1.z, X1.w);
        *(uint4*)(sm + o) = v;
    };

    const int CH = EMB_D / BK;       // 8
    issueB(0, 0); issueB(1, 1);
    {
        float4 X0, X1;
        ldgA(0, X0, X1);
        stsA(0, X0, X1);
    }
    for (int ch = 0; ch < CH; ch++) {
        if (ch + 2 < CH) cp_wait1(); else cp_wait0();
        __syncthreads();
        if (ch + 2 < CH) issueB((ch + 2) % 3, ch + 2);
        float4 X0, X1;
        const bool more = (ch + 1 < CH);
        if (more) ldgA(ch + 1, X0, X1);
        mma_chunk1(sb + (ch % 3) * STG, lane, warp_m, warp_n, acc);
        if (more) stsA((ch + 1) % 3, X0, X1);
    }

    // store fp16 PQ; fold b1 into the P half (global cols < 512)
    #pragma unroll
    for (int mt = 0; mt < 4; mt++)
        #pragma unroll
        for (int h = 0; h < 2; h++) {
            int r = m0 + warp_m * 64 + mt * 16 + (lane >> 2) + 8 * h;
            if (r < n_nodes) {
                #pragma unroll
                for (int nb = 0; nb < 4; nb++) {
                    int c = n0 + warp_n * 32 + nb * 8 + (lane & 3) * 2;
                    float v0 = acc[mt][nb][2 * h];
                    float v1 = acc[mt][nb][2 * h + 1];
                    if (c < 512) { v0 += b1[c]; v1 += b1[c + 1]; }
                    *(__half2*)(g_PQh + (size_t)r * PQN + c) =
                        __floats2half2_rn(v0, v1);
                }
            }
        }
}

// ---------------- GEMM 2+3: h1 on-the-fly, 1-pass GEMM vs W2, relu, dot W3 ----------------
__global__ __launch_bounds__(NT, 1)
void gemm_l23(const int* __restrict__ edge_index,
              const int* __restrict__ move_idx, int n_edges,
              const float* __restrict__ b2,
              const float* __restrict__ W3, const float* __restrict__ b3,
              float* __restrict__ out, int M)
{
    extern __shared__ char sm[];
    const uint32_t sb = smem_u32(sm);
    const int t = threadIdx.x, lane = t & 31, w = t >> 5;
    const int warp_m = w >> 3, warp_n = w & 7;
    const int m0 = blockIdx.x * BM;

    int*   offS = (int*)(sm + AUXO);
    int*   offT = (int*)(sm + AUXO + 512);
    float* b2s  = (float*)(sm + AUXO + 1024);
    float* w3s  = (float*)(sm + AUXO + 2048);
    float* red  = (float*)(sm + AUXO + 4096);   // [128][8]

    if (t < 128) {
        int m = m0 + t; if (m >= M) m = M - 1;
        int e = move_idx[m];
        offS[t] = edge_index[e] * PQN;
        offT[t] = edge_index[n_edges + e] * PQN + 512;
    } else if (t < 384) {
        b2s[t - 128] = b2[t - 128];
    }
    if (t >= 256) w3s[t - 256] = W3[t - 256];
    __syncthreads();

    float acc[4][4][4];
    #pragma unroll
    for (int a = 0; a < 4; a++)
        #pragma unroll
        for (int b = 0; b < 4; b++)
            #pragma unroll
            for (int c = 0; c < 4; c++) acc[a][b][c] = 0.f;

    const int r = t >> 2;            // A row (0..127)
    const int q = t & 3;             // 8-col group within the 32-k chunk

    auto issueB = [&](int stage, int ch) {
        uint32_t sg = sb + stage * STG;
        int k0 = ch * BK;
        #pragma unroll
        for (int i = 0; i < 2; i++) {        // B hi: 1024 cp16
            int g = t + i * NT;
            int row = g >> 2, c = g & 3;
            cp16(sg + BH_O + row * RS + c * 16,
                 g_W2h + (size_t)row * H1DIM + k0 + c * 8);
        }
        cp_commit();
    };
    auto ldgA = [&](int ch, uint4& S, uint4& T) {
        int cb = ch * BK + q * 8;
        S = *(const uint4*)(g_PQh + offS[r] + cb);
        T = *(const uint4*)(g_PQh + offT[r] + cb);
    };
    auto stsA = [&](int stage, const uint4& S, const uint4& T) {
        uint32_t o = stage * STG + A_O + r * RS + q * 16;
        const __half2 z = __floats2half2_rn(0.f, 0.f);
        uint4 v;
        const __half2* s2 = (const __half2*)&S;
        const __half2* t2 = (const __half2*)&T;
        __half2* v2 = (__half2*)&v;
        #pragma unroll
        for (int j = 0; j < 4; j++)
            v2[j] = __hmax2(__hadd2(s2[j], t2[j]), z);
        *(uint4*)(sm + o) = v;
    };

    const int CH = H1DIM / BK;       // 16
    issueB(0, 0); issueB(1, 1);
    {
        uint4 S, T;
        ldgA(0, S, T);
        stsA(0, S, T);
    }
    for (int ch = 0; ch < CH; ch++) {
        if (ch + 2 < CH) cp_wait1(); else cp_wait0();
        __syncthreads();
        if (ch + 2 < CH) issueB((ch + 2) % 3, ch + 2);
        uint4 S, T;
        const bool more = (ch + 1 < CH);
        if (more) ldgA(ch + 1, S, T);
        mma_chunk1(sb + (ch % 3) * STG, lane, warp_m, warp_n, acc);
        if (more) stsA((ch + 1) % 3, S, T);
    }

    // epilogue: +b2, relu, dot w3, quad-reduce, smem partials per warp_n
    #pragma unroll
    for (int mt = 0; mt < 4; mt++)
        #pragma unroll
        for (int h = 0; h < 2; h++) {
            int ri = warp_m * 64 + mt * 16 + (lane >> 2) + 8 * h;   // 0..127
            float p = 0.f;
            #pragma unroll
            for (int nb = 0; nb < 4; nb++) {
                int c = warp_n * 32 + nb * 8 + (lane & 3) * 2;
                float v0 = acc[mt][nb][2 * h]     + b2s[c];
                float v1 = acc[mt][nb][2 * h + 1] + b2s[c + 1];
                v0 = v0 > 0.f ? v0 : 0.f;
                v1 = v1 > 0.f ? v1 : 0.f;
                p += v0 * w3s[c] + v1 * w3s[c + 1];
            }
            p += __shfl_xor_sync(0xffffffffu, p, 1);
            p += __shfl_xor_sync(0xffffffffu, p, 2);
            if ((lane & 3) == 0) red[ri * 8 + warp_n] = p;
        }
    __syncthreads();
    if (t < 128) {
        int m = m0 + t;
        if (m < M) {
            float s = b3[0];
            #pragma unroll
            for (int j = 0; j < 8; j++) s += red[t * 8 + j];
            out[m] = s;
        }
    }
}

// ---------------- launch ----------------
extern "C" void kernel_launch(void* const* d_in, const int* in_sizes, int n_in,
                              void* d_out, int out_size)
{
    const float* emb        = (const float*)d_in[0];
    const int*   edge_index = (const int*)d_in[1];
    const int*   move_idx   = (const int*)d_in[2];
    const float* W1 = (const float*)d_in[3];
    const float* b1 = (const float*)d_in[4];
    const float* W2 = (const float*)d_in[5];
    const float* b2 = (const float*)d_in[6];
    const float* W3 = (const float*)d_in[7];
    const float* b3 = (const float*)d_in[8];
    float* out = (float*)d_out;

    int n_nodes = in_sizes[0] / EMB_D;
    int n_edges = in_sizes[1] / 2;
    int M       = in_sizes[2];
    int mtiles  = (M + BM - 1) / BM;
    int ntiles  = (n_nodes + BM - 1) / BM;

    cudaFuncSetAttribute(gemm_pq,  cudaFuncAttributeMaxDynamicSharedMemorySize, SMEM_TOTAL);
    cudaFuncSetAttribute(gemm_l23, cudaFuncAttributeMaxDynamicSharedMemorySize, SMEM_TOTAL);

    prep_w<<<256, 256>>>(W1, W2);
    {
        dim3 grid(PQN / BN, ntiles);     // 4 x 782
        gemm_pq<<<grid, NT, SMEM_TOTAL>>>(emb, b1, n_nodes);
    }
    gemm_l23<<<mtiles, NT, SMEM_TOTAL>>>(edge_index, move_idx, n_edges,
                                         b2, W3, b3, out, M);
}

// round 13
// speedup vs baseline: 1.9970x; 1.0479x over previous
#include <cuda_runtime.h>
#include <cuda_fp16.h>
#include <cstdint>

// ---------------------------------------------------------------------------
// MovePredictor: logits = W3 . relu(W2 . relu(W1.[e_src;e_tgt] + b1) + b2) + b3
//  - PQ = emb @ [W1_left; W1_right]^T over NODES (b1 folded into P), fp16 out
//  - pq consumes emb fp32 directly (LDG->CVT->STS pipelined A path)
//  - h1[m] = relu(PQ[src,:512] + PQ[tgt,512:]) built on the fly
//  - 1-pass fp16 GEMMs, 512-thread CTAs, 64x32 warp tiles (CTA 128x256),
//    BK=64 (half the syncs), 3-stage cp.async; smem-reduction epilogue.
// ---------------------------------------------------------------------------

#define N_NODES_MAX 100000
#define EMB_D   256
#define H1DIM   512
#define H2DIM   256
#define PQN     1024

#define BM 128
#define BN 256
#define BK 64
#define RS 144                   // 128B data + 16B pad
#define NT 512

// stage layout: A (128x144) + B hi (256x144)
#define A_O   0
#define BH_O  18432
#define STG   55296
#define AUXO  (STG * 3)          // 165888
#define SMEM_TOTAL (AUXO + 8192)

// ---- device globals (allocation-free scratch) ----
__device__ __half g_PQh[(size_t)N_NODES_MAX * PQN];
__device__ __half g_W1sh[(size_t)PQN * EMB_D];
__device__ __half g_W2h[(size_t)H2DIM * H1DIM];

// ---------------- helpers ----------------
__device__ __forceinline__ uint32_t smem_u32(const void* p) {
    uint32_t a;
    asm("{ .reg .u64 t; cvta.to.shared.u64 t, %1; cvt.u32.u64 %0, t; }"
        : "=r"(a) : "l"(p));
    return a;
}
__device__ __forceinline__ void cp16(uint32_t dst, const void* src) {
    asm volatile("cp.async.cg.shared.global [%0], [%1], 16;" :: "r"(dst), "l"(src));
}
__device__ __forceinline__ void cp_commit() {
    asm volatile("cp.async.commit_group;" ::: "memory");
}
__device__ __forceinline__ void cp_wait0() {
    asm volatile("cp.async.wait_group 0;" ::: "memory");
}
__device__ __forceinline__ void cp_wait1() {
    asm volatile("cp.async.wait_group 1;" ::: "memory");
}
__device__ __forceinline__ void ldsm_x4(uint32_t* r, uint32_t addr) {
    asm volatile("ldmatrix.sync.aligned.m8n8.x4.shared.b16 {%0,%1,%2,%3}, [%4];"
                 : "=r"(r[0]), "=r"(r[1]), "=r"(r[2]), "=r"(r[3]) : "r"(addr));
}
__device__ __forceinline__ void mma_f16(float* c, const uint32_t* a,
                                        uint32_t b0, uint32_t b1) {
    asm volatile(
        "mma.sync.aligned.m16n8k16.row.col.f32.f16.f16.f32 "
        "{%0,%1,%2,%3}, {%4,%5,%6,%7}, {%8,%9}, {%0,%1,%2,%3};"
        : "+f"(c[0]), "+f"(c[1]), "+f"(c[2]), "+f"(c[3])
        : "r"(a[0]), "r"(a[1]), "r"(a[2]), "r"(a[3]), "r"(b0), "r"(b1));
}

// 64x32 warp tile over one 64-k chunk (4 k16 steps), 1-pass
__device__ __forceinline__ void mma_chunk1(uint32_t stg, int lane, int warp_m,
                                           int warp_n, float acc[4][4][4]) {
    const uint32_t aB = stg + A_O  + (warp_m * 64 + (lane & 15)) * RS + (lane >> 4) * 16;
    const uint32_t bB = stg + BH_O + (warp_n * 32 + (lane & 15)) * RS + (lane >> 4) * 16;
    #pragma unroll
    for (int kt = 0; kt < 4; kt++) {
        uint32_t aR[4][4], bH[2][4];
        #pragma unroll
        for (int mt = 0; mt < 4; mt++)
            ldsm_x4(aR[mt], aB + mt * 16 * RS + kt * 32);
        #pragma unroll
        for (int nb = 0; nb < 2; nb++)
            ldsm_x4(bH[nb], bB + nb * 16 * RS + kt * 32);
        #pragma unroll
        for (int mt = 0; mt < 4; mt++)
            #pragma unroll
            for (int nb = 0; nb < 2; nb++) {
                mma_f16(acc[mt][2 * nb],     aR[mt], bH[nb][0], bH[nb][2]);
                mma_f16(acc[mt][2 * nb + 1], aR[mt], bH[nb][1], bH[nb][3]);
            }
    }
}

// ---------------- prep: weights only ----------------
__global__ void prep_w(const float* __restrict__ W1, const float* __restrict__ W2)
{
    int total = PQN * EMB_D + H2DIM * H1DIM;     // 393216
    for (int i = blockIdx.x * blockDim.x + threadIdx.x; i < total;
         i += gridDim.x * blockDim.x) {
        if (i < PQN * EMB_D) {
            int r = i >> 8, k = i & 255;
            g_W1sh[i] = __float2half_rn(
                W1[(size_t)(r & 511) * 512 + k + ((r >> 9) << 8)]);
        } else {
            int j = i - PQN * EMB_D;
            g_W2h[j] = __float2half_rn(W2[j]);
        }
    }
}

// ---------------- GEMM 1: PQ = emb @ W1s^T (+b1 on P half), fp16 out ----------------
__global__ __launch_bounds__(NT, 1)
void gemm_pq(const float* __restrict__ emb, const float* __restrict__ b1,
             int n_nodes)
{
    extern __shared__ char sm[];
    const uint32_t sb = smem_u32(sm);
    const int t = threadIdx.x, lane = t & 31, w = t >> 5;
    const int warp_m = w >> 3, warp_n = w & 7;
    const int m0 = blockIdx.y * BM;
    const int n0 = blockIdx.x * BN;

    float acc[4][4][4];
    #pragma unroll
    for (int a = 0; a < 4; a++)
        #pragma unroll
        for (int b = 0; b < 4; b++)
            #pragma unroll
            for (int c = 0; c < 4; c++) acc[a][b][c] = 0.f;

    // A path: per-thread LDG of 16 fp32 -> cvt -> 2x16B STS
    const int ar = t >> 2;           // A row (0..127)
    const int aq = t & 3;            // 16-col group of 64
    int gm = m0 + ar; if (gm >= n_nodes) gm = n_nodes - 1;
    const float* embRow = emb + (size_t)gm * EMB_D + aq * 16;

    auto issueB = [&](int stage, int ch) {
        uint32_t sg = sb + stage * STG;
        int k0 = ch * BK;
        #pragma unroll
        for (int i = 0; i < 4; i++) {        // B hi: 2048 cp16
            int g = t + i * NT;
            int row = g >> 3, c = g & 7;
            cp16(sg + BH_O + row * RS + c * 16,
                 g_W1sh + (size_t)(n0 + row) * EMB_D + k0 + c * 8);
        }
        cp_commit();
    };
    auto ldgA = [&](int ch, float4* X) {
        const float* p = embRow + ch * BK;
        #pragma unroll
        for (int j = 0; j < 4; j++) X[j] = *(const float4*)(p + 4 * j);
    };
    auto stsA = [&](int stage, const float4* X) {
        uint32_t o = stage * STG + A_O + ar * RS + aq * 32;
        uint4 v0, v1;
        __half2* a2 = (__half2*)&v0;
        __half2* b2v = (__half2*)&v1;
        a2[0]  = __floats2half2_rn(X[0].x, X[0].y);
        a2[1]  = __floats2half2_rn(X[0].z, X[0].w);
        a2[2]  = __floats2half2_rn(X[1].x, X[1].y);
        a2[3]  = __floats2half2_rn(X[1].z, X[1].w);
        b2v[0] = __floats2half2_rn(X[2].x, X[2].y);
        b2v[1] = __floats2half2_rn(X[2].z, X[2].w);
        b2v[2] = __floats2half2_rn(X[3].x, X[3].y);
        b2v[3] = __floats2half2_rn(X[3].z, X[3].w);
        *(uint4*)(sm + o)      = v0;
        *(uint4*)(sm + o + 16) = v1;
    };

    const int CH = EMB_D / BK;       // 4
    issueB(0, 0); issueB(1, 1);
    {
        float4 X[4];
        ldgA(0, X);
        stsA(0, X);
    }
    for (int ch = 0; ch < CH; ch++) {
        if (ch + 2 < CH) cp_wait1(); else cp_wait0();
        __syncthreads();
        if (ch + 2 < CH) issueB((ch + 2) % 3, ch + 2);
        float4 X[4];
        const bool more = (ch + 1 < CH);
        if (more) ldgA(ch + 1, X);
        mma_chunk1(sb + (ch % 3) * STG, lane, warp_m, warp_n, acc);
        if (more) stsA((ch + 1) % 3, X);
    }

    // store fp16 PQ; fold b1 into the P half (global cols < 512)
    #pragma unroll
    for (int mt = 0; mt < 4; mt++)
        #pragma unroll
        for (int h = 0; h < 2; h++) {
            int r = m0 + warp_m * 64 + mt * 16 + (lane >> 2) + 8 * h;
            if (r < n_nodes) {
                #pragma unroll
                for (int nb = 0; nb < 4; nb++) {
                    int c = n0 + warp_n * 32 + nb * 8 + (lane & 3) * 2;
                    float v0 = acc[mt][nb][2 * h];
                    float v1 = acc[mt][nb][2 * h + 1];
                    if (c < 512) { v0 += b1[c]; v1 += b1[c + 1]; }
                    *(__half2*)(g_PQh + (size_t)r * PQN + c) =
                        __floats2half2_rn(v0, v1);
                }
            }
        }
}

// ---------------- GEMM 2+3: h1 on-the-fly, 1-pass GEMM vs W2, relu, dot W3 ----------------
__global__ __launch_bounds__(NT, 1)
void gemm_l23(const int* __restrict__ edge_index,
              const int* __restrict__ move_idx, int n_edges,
              const float* __restrict__ b2,
              const float* __restrict__ W3, const float* __restrict__ b3,
              float* __restrict__ out, int M)
{
    extern __shared__ char sm[];
    const uint32_t sb = smem_u32(sm);
    const int t = threadIdx.x, lane = t & 31, w = t >> 5;
    const int warp_m = w >> 3, warp_n = w & 7;
    const int m0 = blockIdx.x * BM;

    int*   offS = (int*)(sm + AUXO);
    int*   offT = (int*)(sm + AUXO + 512);
    float* b2s  = (float*)(sm + AUXO + 1024);
    float* w3s  = (float*)(sm + AUXO + 2048);
    float* red  = (float*)(sm + AUXO + 4096);   // [128][8]

    if (t < 128) {
        int m = m0 + t; if (m >= M) m = M - 1;
        int e = move_idx[m];
        offS[t] = edge_index[e] * PQN;
        offT[t] = edge_index[n_edges + e] * PQN + 512;
    } else if (t < 384) {
        b2s[t - 128] = b2[t - 128];
    }
    if (t >= 256) w3s[t - 256] = W3[t - 256];
    __syncthreads();

    float acc[4][4][4];
    #pragma unroll
    for (int a = 0; a < 4; a++)
        #pragma unroll
        for (int b = 0; b < 4; b++)
            #pragma unroll
            for (int c = 0; c < 4; c++) acc[a][b][c] = 0.f;

    const int r = t >> 2;            // A row (0..127)
    const int q = t & 3;             // 16-col group within the 64-k chunk

    auto issueB = [&](int stage, int ch) {
        uint32_t sg = sb + stage * STG;
        int k0 = ch * BK;
        #pragma unroll
        for (int i = 0; i < 4; i++) {        // B hi: 2048 cp16
            int g = t + i * NT;
            int row = g >> 3, c = g & 7;
            cp16(sg + BH_O + row * RS + c * 16,
                 g_W2h + (size_t)row * H1DIM + k0 + c * 8);
        }
        cp_commit();
    };
    auto ldgA = [&](int ch, uint4* S, uint4* T) {
        int cb = ch * BK + q * 16;
        const __half* ps = g_PQh + offS[r] + cb;
        const __half* pt = g_PQh + offT[r] + cb;
        S[0] = *(const uint4*)ps;
        S[1] = *(const uint4*)(ps + 8);
        T[0] = *(const uint4*)pt;
        T[1] = *(const uint4*)(pt + 8);
    };
    auto stsA = [&](int stage, const uint4* S, const uint4* T) {
        uint32_t o = stage * STG + A_O + r * RS + q * 32;
        const __half2 z = __floats2half2_rn(0.f, 0.f);
        #pragma unroll
        for (int j = 0; j < 2; j++) {
            uint4 v;
            const __half2* s2 = (const __half2*)&S[j];
            const __half2* t2 = (const __half2*)&T[j];
            __half2* v2 = (__half2*)&v;
            #pragma unroll
            for (int k = 0; k < 4; k++)
                v2[k] = __hmax2(__hadd2(s2[k], t2[k]), z);
            *(uint4*)(sm + o + j * 16) = v;
        }
    };

    const int CH = H1DIM / BK;       // 8
    issueB(0, 0); issueB(1, 1);
    {
        uint4 S[2], T[2];
        ldgA(0, S, T);
        stsA(0, S, T);
    }
    for (int ch = 0; ch < CH; ch++) {
        if (ch + 2 < CH) cp_wait1(); else cp_wait0();
        __syncthreads();
        if (ch + 2 < CH) issueB((ch + 2) % 3, ch + 2);
        uint4 S[2], T[2];
        const bool more = (ch + 1 < CH);
        if (more) ldgA(ch + 1, S, T);
        mma_chunk1(sb + (ch % 3) * STG, lane, warp_m, warp_n, acc);
        if (more) stsA((ch + 1) % 3, S, T);
    }

    // epilogue: +b2, relu, dot w3, quad-reduce, smem partials per warp_n
    #pragma unroll
    for (int mt = 0; mt < 4; mt++)
        #pragma unroll
        for (int h = 0; h < 2; h++) {
            int ri = warp_m * 64 + mt * 16 + (lane >> 2) + 8 * h;   // 0..127
            float p = 0.f;
            #pragma unroll
            for (int nb = 0; nb < 4; nb++) {
                int c = warp_n * 32 + nb * 8 + (lane & 3) * 2;
                float v0 = acc[mt][nb][2 * h]     + b2s[c];
                float v1 = acc[mt][nb][2 * h + 1] + b2s[c + 1];
                v0 = v0 > 0.f ? v0 : 0.f;
                v1 = v1 > 0.f ? v1 : 0.f;
                p += v0 * w3s[c] + v1 * w3s[c + 1];
            }
            p += __shfl_xor_sync(0xffffffffu, p, 1);
            p += __shfl_xor_sync(0xffffffffu, p, 2);
            if ((lane & 3) == 0) red[ri * 8 + warp_n] = p;
        }
    __syncthreads();
    if (t < 128) {
        int m = m0 + t;
        if (m < M) {
            float s = b3[0];
            #pragma unroll
            for (int j = 0; j < 8; j++) s += red[t * 8 + j];
            out[m] = s;
        }
    }
}

// ---------------- launch ----------------
extern "C" void kernel_launch(void* const* d_in, const int* in_sizes, int n_in,
                              void* d_out, int out_size)
{
    const float* emb        = (const float*)d_in[0];
    const int*   edge_index = (const int*)d_in[1];
    const int*   move_idx   = (const int*)d_in[2];
    const float* W1 = (const float*)d_in[3];
    const float* b1 = (const float*)d_in[4];
    const float* W2 = (const float*)d_in[5];
    const float* b2 = (const float*)d_in[6];
    const float* W3 = (const float*)d_in[7];
    const float* b3 = (const float*)d_in[8];
    float* out = (float*)d_out;

    int n_nodes = in_sizes[0] / EMB_D;
    int n_edges = in_sizes[1] / 2;
    int M       = in_sizes[2];
    int mtiles  = (M + BM - 1) / BM;
    int ntiles  = (n_nodes + BM - 1) / BM;

    cudaFuncSetAttribute(gemm_pq,  cudaFuncAttributeMaxDynamicSharedMemorySize, SMEM_TOTAL);
    cudaFuncSetAttribute(gemm_l23, cudaFuncAttributeMaxDynamicSharedMemorySize, SMEM_TOTAL);

    prep_w<<<256, 256>>>(W1, W2);
    {
        dim3 grid(PQN / BN, ntiles);     // 4 x 782
        gemm_pq<<<grid, NT, SMEM_TOTAL>>>(emb, b1, n_nodes);
    }
    gemm_l23<<<mtiles, NT, SMEM_TOTAL>>>(edge_index, move_idx, n_edges,
                                         b2, W3, b3, out, M);
}

// round 14
// speedup vs baseline: 2.0131x; 1.0080x over previous
#include <cuda_runtime.h>
#include <cuda_fp16.h>
#include <cstdint>

// ---------------------------------------------------------------------------
// MovePredictor: logits = W3 . relu(W2 . relu(W1.[e_src;e_tgt] + b1) + b2) + b3
//  - PQ = emb @ [W1_left; W1_right]^T over NODES (b1 folded into P), fp16 out
//  - pq consumes emb fp32 directly; h1 built on the fly in l23
//  - 1-pass fp16 GEMMs; 256-thread CTAs, 2 CTAs/SM, CTA tile 64x256,
//    warp tile 64x32 (warp grid 1x8), BK=64, 2-stage cp.async.
// ---------------------------------------------------------------------------

#define N_NODES_MAX 100000
#define EMB_D   256
#define H1DIM   512
#define H2DIM   256
#define PQN     1024

#define BM 64
#define BN 256
#define BK 64
#define RS 144                   // 128B data + 16B pad
#define NT 256

// stage layout: A (64x144) + B hi (256x144)
#define A_O   0
#define BH_O  9216
#define STG   46080
#define AUXO  (STG * 2)          // 92160
#define SMEM_TOTAL (AUXO + 6144)

// ---- device globals (allocation-free scratch) ----
__device__ __half g_PQh[(size_t)N_NODES_MAX * PQN];
__device__ __half g_W1sh[(size_t)PQN * EMB_D];
__device__ __half g_W2h[(size_t)H2DIM * H1DIM];

// ---------------- helpers ----------------
__device__ __forceinline__ uint32_t smem_u32(const void* p) {
    uint32_t a;
    asm("{ .reg .u64 t; cvta.to.shared.u64 t, %1; cvt.u32.u64 %0, t; }"
        : "=r"(a) : "l"(p));
    return a;
}
__device__ __forceinline__ void cp16(uint32_t dst, const void* src) {
    asm volatile("cp.async.cg.shared.global [%0], [%1], 16;" :: "r"(dst), "l"(src));
}
__device__ __forceinline__ void cp_commit() {
    asm volatile("cp.async.commit_group;" ::: "memory");
}
__device__ __forceinline__ void cp_wait0() {
    asm volatile("cp.async.wait_group 0;" ::: "memory");
}
__device__ __forceinline__ void ldsm_x4(uint32_t* r, uint32_t addr) {
    asm volatile("ldmatrix.sync.aligned.m8n8.x4.shared.b16 {%0,%1,%2,%3}, [%4];"
                 : "=r"(r[0]), "=r"(r[1]), "=r"(r[2]), "=r"(r[3]) : "r"(addr));
}
__device__ __forceinline__ void mma_f16(float* c, const uint32_t* a,
                                        uint32_t b0, uint32_t b1) {
    asm volatile(
        "mma.sync.aligned.m16n8k16.row.col.f32.f16.f16.f32 "
        "{%0,%1,%2,%3}, {%4,%5,%6,%7}, {%8,%9}, {%0,%1,%2,%3};"
        : "+f"(c[0]), "+f"(c[1]), "+f"(c[2]), "+f"(c[3])
        : "r"(a[0]), "r"(a[1]), "r"(a[2]), "r"(a[3]), "r"(b0), "r"(b1));
}

// 64x32 warp tile over one 64-k chunk (4 k16 steps), 1-pass
__device__ __forceinline__ void mma_chunk1(uint32_t stg, int lane, int warp_n,
                                           float acc[4][4][4]) {
    const uint32_t aB = stg + A_O  + (lane & 15) * RS + (lane >> 4) * 16;
    const uint32_t bB = stg + BH_O + (warp_n * 32 + (lane & 15)) * RS + (lane >> 4) * 16;
    #pragma unroll
    for (int kt = 0; kt < 4; kt++) {
        uint32_t aR[4][4], bH[2][4];
        #pragma unroll
        for (int mt = 0; mt < 4; mt++)
            ldsm_x4(aR[mt], aB + mt * 16 * RS + kt * 32);
        #pragma unroll
        for (int nb = 0; nb < 2; nb++)
            ldsm_x4(bH[nb], bB + nb * 16 * RS + kt * 32);
        #pragma unroll
        for (int mt = 0; mt < 4; mt++)
            #pragma unroll
            for (int nb = 0; nb < 2; nb++) {
                mma_f16(acc[mt][2 * nb],     aR[mt], bH[nb][0], bH[nb][2]);
                mma_f16(acc[mt][2 * nb + 1], aR[mt], bH[nb][1], bH[nb][3]);
            }
    }
}

// ---------------- prep: weights only ----------------
__global__ void prep_w(const float* __restrict__ W1, const float* __restrict__ W2)
{
    int total = PQN * EMB_D + H2DIM * H1DIM;     // 393216
    for (int i = blockIdx.x * blockDim.x + threadIdx.x; i < total;
         i += gridDim.x * blockDim.x) {
        if (i < PQN * EMB_D) {
            int r = i >> 8, k = i & 255;
            g_W1sh[i] = __float2half_rn(
                W1[(size_t)(r & 511) * 512 + k + ((r >> 9) << 8)]);
        } else {
            int j = i - PQN * EMB_D;
            g_W2h[j] = __float2half_rn(W2[j]);
        }
    }
}

// ---------------- GEMM 1: PQ = emb @ W1s^T (+b1 on P half), fp16 out ----------------
__global__ __launch_bounds__(NT, 2)
void gemm_pq(const float* __restrict__ emb, const float* __restrict__ b1,
             int n_nodes)
{
    extern __shared__ char sm[];
    const uint32_t sb = smem_u32(sm);
    const int t = threadIdx.x, lane = t & 31, warp_n = t >> 5;
    const int m0 = blockIdx.y * BM;
    const int n0 = blockIdx.x * BN;

    float acc[4][4][4];
    #pragma unroll
    for (int a = 0; a < 4; a++)
        #pragma unroll
        for (int b = 0; b < 4; b++)
            #pragma unroll
            for (int c = 0; c < 4; c++) acc[a][b][c] = 0.f;

    // A path: 64 rows x 4 col-groups -> per-thread 16 fp32 LDG, cvt, 2x16B STS
    const int ar = t >> 2;           // A row (0..63)
    const int aq = t & 3;            // 16-col group of 64
    int gm = m0 + ar; if (gm >= n_nodes) gm = n_nodes - 1;
    const float* embRow = emb + (size_t)gm * EMB_D + aq * 16;

    auto issueB = [&](int stage, int ch) {
        uint32_t sg = sb + stage * STG;
        int k0 = ch * BK;
        #pragma unroll
        for (int i = 0; i < 8; i++) {        // B hi: 2048 cp16
            int g = t + i * NT;
            int row = g >> 3, c = g & 7;
            cp16(sg + BH_O + row * RS + c * 16,
                 g_W1sh + (size_t)(n0 + row) * EMB_D + k0 + c * 8);
        }
        cp_commit();
    };
    auto ldgA = [&](int ch, float4* X) {
        const float* p = embRow + ch * BK;
        #pragma unroll
        for (int j = 0; j < 4; j++) X[j] = *(const float4*)(p + 4 * j);
    };
    auto stsA = [&](int stage, const float4* X) {
        uint32_t o = stage * STG + A_O + ar * RS + aq * 32;
        uint4 v0, v1;
        __half2* a2 = (__half2*)&v0;
        __half2* b2v = (__half2*)&v1;
        a2[0]  = __floats2half2_rn(X[0].x, X[0].y);
        a2[1]  = __floats2half2_rn(X[0].z, X[0].w);
        a2[2]  = __floats2half2_rn(X[1].x, X[1].y);
        a2[3]  = __floats2half2_rn(X[1].z, X[1].w);
        b2v[0] = __floats2half2_rn(X[2].x, X[2].y);
        b2v[1] = __floats2half2_rn(X[2].z, X[2].w);
        b2v[2] = __floats2half2_rn(X[3].x, X[3].y);
        b2v[3] = __floats2half2_rn(X[3].z, X[3].w);
        *(uint4*)(sm + o)      = v0;
        *(uint4*)(sm + o + 16) = v1;
    };

    const int CH = EMB_D / BK;       // 4
    issueB(0, 0);
    {
        float4 X[4];
        ldgA(0, X);
        stsA(0, X);
    }
    for (int ch = 0; ch < CH; ch++) {
        cp_wait0();
        __syncthreads();
        const bool more = (ch + 1 < CH);
        if (more) issueB((ch + 1) & 1, ch + 1);
        float4 X[4];
        if (more) ldgA(ch + 1, X);
        mma_chunk1(sb + (ch & 1) * STG, lane, warp_n, acc);
        if (more) stsA((ch + 1) & 1, X);
        __syncthreads();
    }

    // store fp16 PQ; fold b1 into the P half (global cols < 512)
    #pragma unroll
    for (int mt = 0; mt < 4; mt++)
        #pragma unroll
        for (int h = 0; h < 2; h++) {
            int r = m0 + mt * 16 + (lane >> 2) + 8 * h;
            if (r < n_nodes) {
                #pragma unroll
                for (int nb = 0; nb < 4; nb++) {
                    int c = n0 + warp_n * 32 + nb * 8 + (lane & 3) * 2;
                    float v0 = acc[mt][nb][2 * h];
                    float v1 = acc[mt][nb][2 * h + 1];
                    if (c < 512) { v0 += b1[c]; v1 += b1[c + 1]; }
                    *(__half2*)(g_PQh + (size_t)r * PQN + c) =
                        __floats2half2_rn(v0, v1);
                }
            }
        }
}

// ---------------- GEMM 2+3: h1 on-the-fly, 1-pass GEMM vs W2, relu, dot W3 ----------------
__global__ __launch_bounds__(NT, 2)
void gemm_l23(const int* __restrict__ edge_index,
              const int* __restrict__ move_idx, int n_edges,
              const float* __restrict__ b2,
              const float* __restrict__ W3, const float* __restrict__ b3,
              float* __restrict__ out, int M)
{
    extern __shared__ char sm[];
    const uint32_t sb = smem_u32(sm);
    const int t = threadIdx.x, lane = t & 31, warp_n = t >> 5;
    const int m0 = blockIdx.x * BM;

    int*   offS = (int*)(sm + AUXO);            // 64 ints
    int*   offT = (int*)(sm + AUXO + 256);      // 64 ints
    float* b2s  = (float*)(sm + AUXO + 512);    // 256 floats
    float* w3s  = (float*)(sm + AUXO + 1536);   // 256 floats
    float* red  = (float*)(sm + AUXO + 2560);   // [64][8] floats

    if (t < 64) {
        int m = m0 + t; if (m >= M) m = M - 1;
        int e = move_idx[m];
        offS[t] = edge_index[e] * PQN;
        offT[t] = edge_index[n_edges + e] * PQN + 512;
    }
    b2s[t] = b2[t];
    w3s[t] = W3[t];
    __syncthreads();

    float acc[4][4][4];
    #pragma unroll
    for (int a = 0; a < 4; a++)
        #pragma unroll
        for (int b = 0; b < 4; b++)
            #pragma unroll
            for (int c = 0; c < 4; c++) acc[a][b][c] = 0.f;

    const int r = t >> 2;            // A row (0..63)
    const int q = t & 3;             // 16-col group within the 64-k chunk
    const int myS = offS[r];
    const int myT = offT[r];

    auto issueB = [&](int stage, int ch) {
        uint32_t sg = sb + stage * STG;
        int k0 = ch * BK;
        #pragma unroll
        for (int i = 0; i < 8; i++) {        // B hi: 2048 cp16
            int g = t + i * NT;
            int row = g >> 3, c = g & 7;
            cp16(sg + BH_O + row * RS + c * 16,
                 g_W2h + (size_t)row * H1DIM + k0 + c * 8);
        }
        cp_commit();
    };
    auto ldgA = [&](int ch, uint4* S, uint4* T) {
        int cb = ch * BK + q * 16;
        const __half* ps = g_PQh + myS + cb;
        const __half* pt = g_PQh + myT + cb;
        S[0] = *(const uint4*)ps;
        S[1] = *(const uint4*)(ps + 8);
        T[0] = *(const uint4*)pt;
        T[1] = *(const uint4*)(pt + 8);
    };
    auto stsA = [&](int stage, const uint4* S, const uint4* T) {
        uint32_t o = stage * STG + A_O + r * RS + q * 32;
        const __half2 z = __floats2half2_rn(0.f, 0.f);
        #pragma unroll
        for (int j = 0; j < 2; j++) {
            uint4 v;
            const __half2* s2 = (const __half2*)&S[j];
            const __half2* t2 = (const __half2*)&T[j];
            __half2* v2 = (__half2*)&v;
            #pragma unroll
            for (int k = 0; k < 4; k++)
                v2[k] = __hmax2(__hadd2(s2[k], t2[k]), z);
            *(uint4*)(sm + o + j * 16) = v;
        }
    };

    const int CH = H1DIM / BK;       // 8
    issueB(0, 0);
    {
        uint4 S[2], T[2];
        ldgA(0, S, T);
        stsA(0, S, T);
    }
    for (int ch = 0; ch < CH; ch++) {
        cp_wait0();
        __syncthreads();
        const bool more = (ch + 1 < CH);
        if (more) issueB((ch + 1) & 1, ch + 1);
        uint4 S[2], T[2];
        if (more) ldgA(ch + 1, S, T);
        mma_chunk1(sb + (ch & 1) * STG, lane, warp_n, acc);
        if (more) stsA((ch + 1) & 1, S, T);
        __syncthreads();
    }

    // epilogue: +b2, relu, dot w3, quad-reduce, smem partials per warp_n
    #pragma unroll
    for (int mt = 0; mt < 4; mt++)
        #pragma unroll
        for (int h = 0; h < 2; h++) {
            int ri = mt * 16 + (lane >> 2) + 8 * h;   // 0..63
            float p = 0.f;
            #pragma unroll
            for (int nb = 0; nb < 4; nb++) {
                int c = warp_n * 32 + nb * 8 + (lane & 3) * 2;
                float v0 = acc[mt][nb][2 * h]     + b2s[c];
                float v1 = acc[mt][nb][2 * h + 1] + b2s[c + 1];
                v0 = v0 > 0.f ? v0 : 0.f;
                v1 = v1 > 0.f ? v1 : 0.f;
                p += v0 * w3s[c] + v1 * w3s[c + 1];
            }
            p += __shfl_xor_sync(0xffffffffu, p, 1);
            p += __shfl_xor_sync(0xffffffffu, p, 2);
            if ((lane & 3) == 0) red[ri * 8 + warp_n] = p;
        }
    __syncthreads();
    if (t < 64) {
        int m = m0 + t;
        if (m < M) {
            float s = b3[0];
            #pragma unroll
            for (int j = 0; j < 8; j++) s += red[t * 8 + j];
            out[m] = s;
        }
    }
}

// ---------------- launch ----------------
extern "C" void kernel_launch(void* const* d_in, const int* in_sizes, int n_in,
                              void* d_out, int out_size)
{
    const float* emb        = (const float*)d_in[0];
    const int*   edge_index = (const int*)d_in[1];
    const int*   move_idx   = (const int*)d_in[2];
    const float* W1 = (const float*)d_in[3];
    const float* b1 = (const float*)d_in[4];
    const float* W2 = (const float*)d_in[5];
    const float* b2 = (const float*)d_in[6];
    const float* W3 = (const float*)d_in[7];
    const float* b3 = (const float*)d_in[8];
    float* out = (float*)d_out;

    int n_nodes = in_sizes[0] / EMB_D;
    int n_edges = in_sizes[1] / 2;
    int M       = in_sizes[2];
    int mtiles  = (M + BM - 1) / BM;
    int ntiles  = (n_nodes + BM - 1) / BM;

    cudaFuncSetAttribute(gemm_pq,  cudaFuncAttributeMaxDynamicSharedMemorySize, SMEM_TOTAL);
    cudaFuncSetAttribute(gemm_l23, cudaFuncAttributeMaxDynamicSharedMemorySize, SMEM_TOTAL);

    prep_w<<<256, 256>>>(W1, W2);
    {
        dim3 grid(PQN / BN, ntiles);     // 4 x 1563
        gemm_pq<<<grid, NT, SMEM_TOTAL>>>(emb, b1, n_nodes);
    }
    gemm_l23<<<mtiles, NT, SMEM_TOTAL>>>(edge_index, move_idx, n_edges,
                                         b2, W3, b3, out, M);
}